// round 15
// baseline (speedup 1.0000x reference)
#include <cuda_runtime.h>
#include <cuda_fp16.h>
#include <cstdint>
#include <cstddef>

#define BB 8
#define SS 2048
#define DD 1024
#define ND 3072   // merged QKV output width

typedef __half fp16;

// ---------------- scratch ----------------
__device__ fp16 g_xh[(size_t)BB * SS * DD];      // x rounded to fp16
__device__ fp16 g_Wt[(size_t)ND * DD];           // [3072][1024] K-major, rounded fp16
__device__ float g_bias[ND];
__device__ fp16 g_QKVh[(size_t)BB * SS * ND];    // [16384][3072]
__device__ fp16 g_Vt[(size_t)BB * DD * SS];      // [b][d][s]
__device__ fp16 g_Pu[(size_t)BB * SS * SS];      // unnormalized exp(scores), fp16
__device__ float g_rsinv[(size_t)BB * SS];       // 1 / rowsum(exp(scores))

// ---------------- PTX helpers ----------------
__device__ __forceinline__ uint32_t smem_u32(const void* p) {
    uint32_t a;
    asm("{ .reg .u64 t; cvta.to.shared.u64 t, %1; cvt.u32.u64 %0, t; }" : "=r"(a) : "l"(p));
    return a;
}
__device__ __forceinline__ void cp16(uint32_t s, const void* g) {
    asm volatile("cp.async.cg.shared.global [%0], [%1], 16;\n" :: "r"(s), "l"(g));
}
__device__ __forceinline__ void cp_commit() { asm volatile("cp.async.commit_group;\n" ::: "memory"); }
template <int N> __device__ __forceinline__ void cp_wait() {
    asm volatile("cp.async.wait_group %0;\n" :: "n"(N) : "memory");
}
__device__ __forceinline__ void ldsm_x4(uint32_t& r0, uint32_t& r1, uint32_t& r2, uint32_t& r3, uint32_t a) {
    asm volatile("ldmatrix.sync.aligned.m8n8.x4.shared.b16 {%0,%1,%2,%3}, [%4];"
                 : "=r"(r0), "=r"(r1), "=r"(r2), "=r"(r3) : "r"(a));
}
__device__ __forceinline__ void mma16816(float* d,
                                         uint32_t a0, uint32_t a1, uint32_t a2, uint32_t a3,
                                         uint32_t b0, uint32_t b1) {
    asm volatile("mma.sync.aligned.m16n8k16.row.col.f32.f16.f16.f32 "
                 "{%0,%1,%2,%3}, {%4,%5,%6,%7}, {%8,%9}, {%0,%1,%2,%3};"
                 : "+f"(d[0]), "+f"(d[1]), "+f"(d[2]), "+f"(d[3])
                 : "r"(a0), "r"(a1), "r"(a2), "r"(a3), "r"(b0), "r"(b1));
}

#define SW128(o) ((o) ^ (((o) >> 3) & 0x70))

// smem stage: A (16K) + B (16K) = 32K; 3 stages = 96K; 2 CTAs/SM
static constexpr int S_A = 0, S_B = 16384;
static constexpr int STAGE = 32768;
static constexpr int STAGES = 3;
static constexpr int SMEM_TOTAL = STAGES * STAGE;   // 98304

// ---------------- 1-pass fp16 mma.sync GEMM, CTA 128x128, 256 thr, warp 64x32 ----------------
// Fragment double-buffering within the chunk AND cross-chunk ks=0 prefetch:
// the end-of-chunk cp_wait<1>+barrier proves stage c+1 complete, so next chunk's
// first fragments are loaded BEFORE its MMAs ever wait on them.
// EPI: 1 = fp16 out (+bias)        [QKV projection]
//      2 = fp16 exp(scale*acc) out [scores -> unnormalized P]
//      3 = fp32 out * rsinv[row]   [PV with deferred softmax normalization]
template <int EPI, bool HASB>
__global__ __launch_bounds__(256, 2)
void tc_gemm(const fp16* __restrict__ A_, const fp16* __restrict__ B_,
             const float* __restrict__ bias, const float* __restrict__ rs,
             float* __restrict__ Co, fp16* __restrict__ Coh,
             int Kd, int lda, int ldb,
             long long sA, long long sB, long long sC, int ldo, float scale)
{
    extern __shared__ char smem[];
    const uint32_t su = smem_u32(smem);
    const int tid = threadIdx.x, lane = tid & 31, wid = tid >> 5;
    const int wm = wid >> 2, wn = wid & 3;           // 2(m) x 4(n), warp tile 64x32
    const int rowBase = blockIdx.y * 128, colBase = blockIdx.x * 128;

    A_ += (long long)blockIdx.z * sA;
    B_ += (long long)blockIdx.z * sB;
    if (EPI == 3) { Co += (long long)blockIdx.z * sC; rs += (long long)blockIdx.z * SS; }
    else          Coh += (long long)blockIdx.z * sC;

    float acc[16][4] = {};                            // [im*4+in][4]

    const int NC = Kd >> 6;

    auto load_stage = [&](int s, int k0) {
        const uint32_t base = su + s * STAGE;
        #pragma unroll
        for (int j = 0; j < 4; ++j) {                 // A: 128 rows x 64 fp16
            const int idx = tid + j * 256, r = idx >> 3, cu = idx & 7;
            const size_t go = (size_t)(rowBase + r) * lda + k0 + cu * 8;
            const uint32_t so = SW128((uint32_t)(r * 128 + cu * 16));
            cp16(base + S_A + so, A_ + go);
        }
        #pragma unroll
        for (int j = 0; j < 4; ++j) {                 // B: 128 rows x 64 fp16
            const int idx = tid + j * 256, r = idx >> 3, cu = idx & 7;
            const size_t go = (size_t)(colBase + r) * ldb + k0 + cu * 8;
            const uint32_t so = SW128((uint32_t)(r * 128 + cu * 16));
            cp16(base + S_B + so, B_ + go);
        }
        cp_commit();
    };

    const uint32_t sw   = (lane & 7) << 4;
    const uint32_t arow = (lane & 7) + (lane & 8);
    const uint32_t koff = (lane & 16);

    uint32_t ah[2][4][4], bh[2][2][4];                // double-buffered fragments

    auto ld_frags = [&](int buf, uint32_t base, int ks) {
        #pragma unroll
        for (int im = 0; im < 4; ++im) {
            const uint32_t off = (wm * 64 + im * 16 + arow) * 128 + ks * 32 + koff;
            ldsm_x4(ah[buf][im][0], ah[buf][im][1], ah[buf][im][2], ah[buf][im][3],
                    (base + S_A + off) ^ sw);
        }
        #pragma unroll
        for (int ip = 0; ip < 2; ++ip) {
            const uint32_t off = (wn * 32 + ip * 16 + arow) * 128 + ks * 32 + koff;
            ldsm_x4(bh[buf][ip][0], bh[buf][ip][1], bh[buf][ip][2], bh[buf][ip][3],
                    (base + S_B + off) ^ sw);
        }
    };

    load_stage(0, 0);
    load_stage(1, 64);
    cp_wait<1>();                                     // my group 0 done
    __syncthreads();                                  // everyone's group 0 done
    ld_frags(0, su, 0);                               // chunk 0, ks=0 warm

    for (int c = 0; c < NC; ++c) {
        const uint32_t base = su + (c % STAGES) * STAGE;
        if (c + 2 < NC) load_stage((c + 2) % STAGES, (c + 2) << 6);
        else            cp_commit();                  // keep group counts aligned

        #pragma unroll
        for (int ks = 0; ks < 4; ++ks) {
            const int cur = ks & 1;
            if (ks < 3) ld_frags(cur ^ 1, base, ks + 1);   // same-chunk prefetch
            #pragma unroll
            for (int im = 0; im < 4; ++im)
                #pragma unroll
                for (int in = 0; in < 4; ++in) {
                    float* d = acc[im * 4 + in];
                    const int ip = in >> 1, sb = in & 1;
                    mma16816(d, ah[cur][im][0], ah[cur][im][1], ah[cur][im][2], ah[cur][im][3],
                             bh[cur][ip][sb], bh[cur][ip][2 + sb]);
                }
        }

        cp_wait<1>();                                 // group c+1 (all but newest) done
        __syncthreads();                              // all warps done reading stage c
        if (c + 1 < NC)
            ld_frags(0, su + ((c + 1) % STAGES) * STAGE, 0);   // next chunk ks=0 warm
    }

    // ---------------- epilogue ----------------
    #pragma unroll
    for (int im = 0; im < 4; ++im) {
        #pragma unroll
        for (int in = 0; in < 4; ++in) {
            const float* d = acc[im * 4 + in];
            const int row0 = rowBase + wm * 64 + im * 16 + (lane >> 2);
            const int col0 = colBase + wn * 32 + in * 8 + 2 * (lane & 3);
            #pragma unroll
            for (int h = 0; h < 2; ++h) {
                const int row = row0 + h * 8;
                float v0 = d[2 * h + 0], v1 = d[2 * h + 1];
                if (HASB) { v0 += bias[col0]; v1 += bias[col0 + 1]; }
                v0 *= scale; v1 *= scale;
                if (EPI == 1) {
                    __half2 H; H.x = __float2half(v0); H.y = __float2half(v1);
                    *reinterpret_cast<__half2*>(Coh + (size_t)row * ldo + col0) = H;
                } else if (EPI == 2) {
                    __half2 H;
                    H.x = __float2half(__expf(v0));
                    H.y = __float2half(__expf(v1));
                    *reinterpret_cast<__half2*>(Coh + (size_t)row * ldo + col0) = H;
                } else {
                    const float r = rs[row];
                    float2 f2; f2.x = v0 * r; f2.y = v1 * r;
                    *reinterpret_cast<float2*>(Co + (size_t)row * ldo + col0) = f2;
                }
            }
        }
    }
}

// ---------------- aux kernels ----------------
__global__ __launch_bounds__(256)
void round_x_kernel(const float4* __restrict__ src, fp16* __restrict__ hi, int n4)
{
    const int i = blockIdx.x * 256 + threadIdx.x;
    if (i >= n4) return;
    const float4 v = src[i];
    __half2 H0; H0.x = __float2half(v.x); H0.y = __float2half(v.y);
    __half2 H1; H1.x = __float2half(v.z); H1.y = __float2half(v.w);
    reinterpret_cast<__half2*>(hi)[2 * i] = H0;
    reinterpret_cast<__half2*>(hi)[2 * i + 1] = H1;
}

// all three W [1024][1024] fp32 -> Wt sections [n][k] fp16 (z selects the matrix)
__global__ __launch_bounds__(256)
void transpose_round_w_all(const float* __restrict__ Wq, const float* __restrict__ Wk,
                           const float* __restrict__ Wv, fp16* __restrict__ T)
{
    __shared__ float t[32][33];
    const float* W = (blockIdx.z == 0) ? Wq : (blockIdx.z == 1) ? Wk : Wv;
    fp16* Td = T + (size_t)blockIdx.z * DD * DD;
    const int tx = threadIdx.x, ty = threadIdx.y;
    const int x0 = blockIdx.x * 32, y0 = blockIdx.y * 32;
    #pragma unroll
    for (int j = 0; j < 32; j += 8)
        t[ty + j][tx] = W[(size_t)(y0 + ty + j) * DD + x0 + tx];
    __syncthreads();
    #pragma unroll
    for (int j = 0; j < 32; j += 8)
        Td[(size_t)(x0 + ty + j) * DD + y0 + tx] = __float2half(t[tx][ty + j]);
}

__global__ void concat_bias(const float* bq, const float* bk, const float* bv, float* o)
{
    const int i = blockIdx.x * 256 + threadIdx.x;
    if (i < DD) o[i] = bq[i];
    else if (i < 2 * DD) o[i] = bk[i - DD];
    else if (i < ND) o[i] = bv[i - 2 * DD];
}

// V slice of QKVh (cols 2048..3071) -> Vt[b][d][s]
__global__ __launch_bounds__(256)
void transpose_v(const fp16* __restrict__ Vh, fp16* __restrict__ Vt)
{
    __shared__ fp16 t[32][33];
    const int tx = threadIdx.x, ty = threadIdx.y;
    const int d0 = blockIdx.x * 32, s0 = blockIdx.y * 32;
    const size_t rowOff = (size_t)blockIdx.z * SS;
    #pragma unroll
    for (int j = 0; j < 32; j += 8)
        t[ty + j][tx] = Vh[(rowOff + s0 + ty + j) * ND + 2 * DD + d0 + tx];
    __syncthreads();
    const size_t bo = (size_t)blockIdx.z * DD * SS;
    #pragma unroll
    for (int j = 0; j < 32; j += 8)
        Vt[bo + (size_t)(d0 + ty + j) * SS + s0 + tx] = t[tx][ty + j];
}

// 1 / rowsum of unnormalized P (fp16 in, fp32 out); one block per row
__global__ __launch_bounds__(256)
void rowsum_inv_kernel(const fp16* __restrict__ Pu, float* __restrict__ rsinv)
{
    __shared__ float red[256];
    const __half2* row = reinterpret_cast<const __half2*>(Pu + (size_t)blockIdx.x * SS);
    const int tid = threadIdx.x;
    float sum = 0.f;
    #pragma unroll
    for (int i = 0; i < 4; ++i) {
        const float2 p = __half22float2(row[tid + 256 * i]);
        sum += p.x + p.y;
    }
    red[tid] = sum; __syncthreads();
    #pragma unroll
    for (int s = 128; s > 0; s >>= 1) { if (tid < s) red[tid] += red[tid + s]; __syncthreads(); }
    if (tid == 0) rsinv[blockIdx.x] = __frcp_rn(red[0]);
}

// ---------------- launch ----------------
extern "C" void kernel_launch(void* const* d_in, const int* in_sizes, int n_in,
                              void* d_out, int out_size)
{
    const float* x  = (const float*)d_in[0];
    const float* Wq = (const float*)d_in[1];
    const float* bq = (const float*)d_in[2];
    const float* Wk = (const float*)d_in[3];
    const float* bk = (const float*)d_in[4];
    const float* Wv = (const float*)d_in[5];
    const float* bv = (const float*)d_in[6];
    float* out = (float*)d_out;

    fp16 *xh, *Wt, *QKVh, *Vt, *Pu;
    float *bias, *rsinv;
    cudaGetSymbolAddress((void**)&xh, g_xh);
    cudaGetSymbolAddress((void**)&Wt, g_Wt);
    cudaGetSymbolAddress((void**)&QKVh, g_QKVh);
    cudaGetSymbolAddress((void**)&Vt, g_Vt);
    cudaGetSymbolAddress((void**)&Pu, g_Pu);
    cudaGetSymbolAddress((void**)&bias, g_bias);
    cudaGetSymbolAddress((void**)&rsinv, g_rsinv);

    cudaFuncSetAttribute(tc_gemm<1, true>,  cudaFuncAttributeMaxDynamicSharedMemorySize, SMEM_TOTAL);
    cudaFuncSetAttribute(tc_gemm<2, false>, cudaFuncAttributeMaxDynamicSharedMemorySize, SMEM_TOTAL);
    cudaFuncSetAttribute(tc_gemm<3, false>, cudaFuncAttributeMaxDynamicSharedMemorySize, SMEM_TOTAL);

    const long long sQK = (long long)SS * ND;
    const long long sS  = (long long)SS * SS;

    // prep: 3 launches
    round_x_kernel<<<(BB * SS * DD / 4 + 255) / 256, 256>>>((const float4*)x, xh, BB * SS * DD / 4);
    transpose_round_w_all<<<dim3(DD / 32, DD / 32, 3), dim3(32, 8)>>>(Wq, Wk, Wv, Wt);
    concat_bias<<<(ND + 255) / 256, 256>>>(bq, bk, bv, bias);

    // merged QKV projection [16384,3072], fp16 out   (ncu -s 5 lands here)
    dim3 g1(ND / 128, BB * SS / 128, 1);                 // (24, 128)
    tc_gemm<1, true><<<g1, 256, SMEM_TOTAL>>>(xh, Wt, bias, nullptr, nullptr, QKVh,
                                              DD, DD, DD, 0, 0, 0, ND, 1.0f);

    // V -> Vt [b][d][s]
    transpose_v<<<dim3(DD / 32, SS / 32, BB), dim3(32, 8)>>>(QKVh, Vt);

    // Pu = exp((Q K^T)/32), fp16 out — fused softmax numerator
    dim3 g2(SS / 128, SS / 128, BB);                     // (16, 16, 8)
    tc_gemm<2, false><<<g2, 256, SMEM_TOTAL>>>(QKVh, QKVh + DD, nullptr, nullptr,
                                               nullptr, Pu,
                                               DD, ND, ND, sQK, sQK, sS, SS, 0.03125f);

    // rsinv = 1 / rowsum(Pu)
    rowsum_inv_kernel<<<BB * SS, 256>>>(Pu, rsinv);

    // out = (Pu V) * rsinv
    dim3 g3(DD / 128, SS / 128, BB);                     // (8, 16, 8)
    tc_gemm<3, false><<<g3, 256, SMEM_TOTAL>>>(Pu, Vt, nullptr, rsinv,
                                               out, nullptr,
                                               SS, SS, SS, sS, (long long)DD * SS,
                                               (long long)SS * DD, DD, 1.0f);
}

// round 16
// speedup vs baseline: 1.0497x; 1.0497x over previous
#include <cuda_runtime.h>
#include <cuda_fp16.h>
#include <cstdint>
#include <cstddef>

#define BB 8
#define SS 2048
#define DD 1024
#define ND 3072   // merged QKV output width

typedef __half fp16;

// ---------------- scratch ----------------
__device__ fp16 g_xh[(size_t)BB * SS * DD];      // x rounded to fp16
__device__ fp16 g_Wt[(size_t)ND * DD];           // [3072][1024] K-major, rounded fp16
__device__ float g_bias[ND];
__device__ fp16 g_QKVh[(size_t)BB * SS * ND];    // [16384][3072]
__device__ fp16 g_Vt[(size_t)BB * DD * SS];      // [b][d][s]
__device__ fp16 g_Pu[(size_t)BB * SS * SS];      // unnormalized exp(scores), fp16
__device__ float g_rsinv[(size_t)BB * SS];       // 1 / rowsum(exp(scores))

// ---------------- PTX helpers ----------------
__device__ __forceinline__ uint32_t smem_u32(const void* p) {
    uint32_t a;
    asm("{ .reg .u64 t; cvta.to.shared.u64 t, %1; cvt.u32.u64 %0, t; }" : "=r"(a) : "l"(p));
    return a;
}
__device__ __forceinline__ void cp16(uint32_t s, const void* g) {
    asm volatile("cp.async.cg.shared.global [%0], [%1], 16;\n" :: "r"(s), "l"(g));
}
__device__ __forceinline__ void cp_commit() { asm volatile("cp.async.commit_group;\n" ::: "memory"); }
template <int N> __device__ __forceinline__ void cp_wait() {
    asm volatile("cp.async.wait_group %0;\n" :: "n"(N) : "memory");
}
__device__ __forceinline__ void ldsm_x4(uint32_t& r0, uint32_t& r1, uint32_t& r2, uint32_t& r3, uint32_t a) {
    asm volatile("ldmatrix.sync.aligned.m8n8.x4.shared.b16 {%0,%1,%2,%3}, [%4];"
                 : "=r"(r0), "=r"(r1), "=r"(r2), "=r"(r3) : "r"(a));
}
__device__ __forceinline__ void mma16816(float* d,
                                         uint32_t a0, uint32_t a1, uint32_t a2, uint32_t a3,
                                         uint32_t b0, uint32_t b1) {
    asm volatile("mma.sync.aligned.m16n8k16.row.col.f32.f16.f16.f32 "
                 "{%0,%1,%2,%3}, {%4,%5,%6,%7}, {%8,%9}, {%0,%1,%2,%3};"
                 : "+f"(d[0]), "+f"(d[1]), "+f"(d[2]), "+f"(d[3])
                 : "r"(a0), "r"(a1), "r"(a2), "r"(a3), "r"(b0), "r"(b1));
}

#define SW128(o) ((o) ^ (((o) >> 3) & 0x70))

// smem stage: A (16K) + B (16K) = 32K; 3 stages = 96K; 2 CTAs/SM
static constexpr int STAGE = 32768;
static constexpr int STAGES = 3;
static constexpr int SMEM_TOTAL = STAGES * STAGE;   // 98304

// ---------------- 1-pass fp16 mma.sync GEMM, CTA 128x128, 256 thr, warp 64x32 ----------------
// Mainloop addressing strength-reduced: running global pointers, precomputed
// swizzled smem offsets (qa/qb per ks), cycling stage-base registers.
// EPI: 1 = fp16 out (+bias)        [QKV projection]
//      2 = fp16 exp(scale*acc) out [scores -> unnormalized P]
//      3 = fp32 out * rsinv[row]   [PV with deferred softmax normalization]
template <int EPI, bool HASB>
__global__ __launch_bounds__(256, 2)
void tc_gemm(const fp16* __restrict__ A_, const fp16* __restrict__ B_,
             const float* __restrict__ bias, const float* __restrict__ rs,
             float* __restrict__ Co, fp16* __restrict__ Coh,
             int Kd, int lda, int ldb,
             long long sA, long long sB, long long sC, int ldo, float scale)
{
    extern __shared__ char smem[];
    const uint32_t su = smem_u32(smem);
    const int tid = threadIdx.x, lane = tid & 31, wid = tid >> 5;
    const int wm = wid >> 2, wn = wid & 3;           // 2(m) x 4(n), warp tile 64x32
    const int rowBase = blockIdx.y * 128, colBase = blockIdx.x * 128;

    A_ += (long long)blockIdx.z * sA;
    B_ += (long long)blockIdx.z * sB;
    if (EPI == 3) { Co += (long long)blockIdx.z * sC; rs += (long long)blockIdx.z * SS; }
    else          Coh += (long long)blockIdx.z * sC;

    // ---- per-thread running global pointers (advance 64 elems per chunk) ----
    const int r0 = tid >> 3, cu8 = (tid & 7) * 8;
    const fp16* aptr = A_ + (size_t)(rowBase + r0) * lda + cu8;
    const fp16* bptr = B_ + (size_t)(colBase + r0) * ldb + cu8;
    const size_t aj = (size_t)32 * lda, bj = (size_t)32 * ldb;   // j-stride (32 rows)

    // ---- precomputed swizzled smem store offset (j adds 4096, commutes with SW128) ----
    const uint32_t st0 = SW128((uint32_t)(r0 * 128 + (tid & 7) * 16));
    uint32_t wbase = su;                               // write-stage base, cycles

    auto load_stage = [&]() {
        #pragma unroll
        for (int j = 0; j < 4; ++j)
            cp16(wbase + st0 + j * 4096, aptr + j * aj);
        #pragma unroll
        for (int j = 0; j < 4; ++j)
            cp16(wbase + 16384 + st0 + j * 4096, bptr + j * bj);
        cp_commit();
        aptr += 64; bptr += 64;
        wbase += STAGE; if (wbase == su + SMEM_TOTAL) wbase = su;
    };

    // ---- precomputed swizzled fragment-read offsets per ks ----
    const uint32_t sw   = (lane & 7) << 4;
    const uint32_t arow = (lane & 7) + (lane & 8);
    const uint32_t koff = (lane & 16);
    uint32_t qa[4], qb[4];
    #pragma unroll
    for (int ks = 0; ks < 4; ++ks) {
        qa[ks] = (((uint32_t)(wm * 64 + arow) * 128) + ks * 32 + koff) ^ sw;
        qb[ks] = ((((uint32_t)(wn * 32 + arow) * 128) + ks * 32 + koff) ^ sw) + 16384;
    }

    float acc[16][4] = {};                             // [im*4+in][4]
    const int NC = Kd >> 6;

    load_stage();
    load_stage();
    uint32_t rbase = su;                               // read-stage base, cycles

    for (int c = 0; c < NC; ++c) {
        cp_wait<1>();
        __syncthreads();                               // single barrier per chunk
        if (c + 2 < NC) load_stage();
        else            cp_commit();                   // keep group counts aligned

        #pragma unroll
        for (int ks = 0; ks < 4; ++ks) {
            uint32_t ah[4][4], bh[2][4];
            #pragma unroll
            for (int im = 0; im < 4; ++im)
                ldsm_x4(ah[im][0], ah[im][1], ah[im][2], ah[im][3],
                        rbase + qa[ks] + im * 2048);
            #pragma unroll
            for (int ip = 0; ip < 2; ++ip)
                ldsm_x4(bh[ip][0], bh[ip][1], bh[ip][2], bh[ip][3],
                        rbase + qb[ks] + ip * 2048);
            #pragma unroll
            for (int im = 0; im < 4; ++im)
                #pragma unroll
                for (int in = 0; in < 4; ++in) {
                    float* d = acc[im * 4 + in];
                    const int ip = in >> 1, sb = in & 1;
                    mma16816(d, ah[im][0], ah[im][1], ah[im][2], ah[im][3],
                             bh[ip][sb], bh[ip][2 + sb]);
                }
        }
        rbase += STAGE; if (rbase == su + SMEM_TOTAL) rbase = su;
    }

    // ---------------- epilogue ----------------
    #pragma unroll
    for (int im = 0; im < 4; ++im) {
        #pragma unroll
        for (int in = 0; in < 4; ++in) {
            const float* d = acc[im * 4 + in];
            const int row0 = rowBase + wm * 64 + im * 16 + (lane >> 2);
            const int col0 = colBase + wn * 32 + in * 8 + 2 * (lane & 3);
            #pragma unroll
            for (int h = 0; h < 2; ++h) {
                const int row = row0 + h * 8;
                float v0 = d[2 * h + 0], v1 = d[2 * h + 1];
                if (HASB) { v0 += bias[col0]; v1 += bias[col0 + 1]; }
                v0 *= scale; v1 *= scale;
                if (EPI == 1) {
                    __half2 H; H.x = __float2half(v0); H.y = __float2half(v1);
                    *reinterpret_cast<__half2*>(Coh + (size_t)row * ldo + col0) = H;
                } else if (EPI == 2) {
                    __half2 H;
                    H.x = __float2half(__expf(v0));
                    H.y = __float2half(__expf(v1));
                    *reinterpret_cast<__half2*>(Coh + (size_t)row * ldo + col0) = H;
                } else {
                    const float r = rs[row];
                    float2 f2; f2.x = v0 * r; f2.y = v1 * r;
                    *reinterpret_cast<float2*>(Co + (size_t)row * ldo + col0) = f2;
                }
            }
        }
    }
}

// ---------------- aux kernels ----------------
__global__ __launch_bounds__(256)
void round_x_kernel(const float4* __restrict__ src, fp16* __restrict__ hi, int n4)
{
    const int i = blockIdx.x * 256 + threadIdx.x;
    if (i >= n4) return;
    const float4 v = src[i];
    __half2 H0; H0.x = __float2half(v.x); H0.y = __float2half(v.y);
    __half2 H1; H1.x = __float2half(v.z); H1.y = __float2half(v.w);
    reinterpret_cast<__half2*>(hi)[2 * i] = H0;
    reinterpret_cast<__half2*>(hi)[2 * i + 1] = H1;
}

// all three W [1024][1024] fp32 -> Wt sections [n][k] fp16 (z selects the matrix)
__global__ __launch_bounds__(256)
void transpose_round_w_all(const float* __restrict__ Wq, const float* __restrict__ Wk,
                           const float* __restrict__ Wv, fp16* __restrict__ T)
{
    __shared__ float t[32][33];
    const float* W = (blockIdx.z == 0) ? Wq : (blockIdx.z == 1) ? Wk : Wv;
    fp16* Td = T + (size_t)blockIdx.z * DD * DD;
    const int tx = threadIdx.x, ty = threadIdx.y;
    const int x0 = blockIdx.x * 32, y0 = blockIdx.y * 32;
    #pragma unroll
    for (int j = 0; j < 32; j += 8)
        t[ty + j][tx] = W[(size_t)(y0 + ty + j) * DD + x0 + tx];
    __syncthreads();
    #pragma unroll
    for (int j = 0; j < 32; j += 8)
        Td[(size_t)(x0 + ty + j) * DD + y0 + tx] = __float2half(t[tx][ty + j]);
}

__global__ void concat_bias(const float* bq, const float* bk, const float* bv, float* o)
{
    const int i = blockIdx.x * 256 + threadIdx.x;
    if (i < DD) o[i] = bq[i];
    else if (i < 2 * DD) o[i] = bk[i - DD];
    else if (i < ND) o[i] = bv[i - 2 * DD];
}

// V slice of QKVh (cols 2048..3071) -> Vt[b][d][s]
__global__ __launch_bounds__(256)
void transpose_v(const fp16* __restrict__ Vh, fp16* __restrict__ Vt)
{
    __shared__ fp16 t[32][33];
    const int tx = threadIdx.x, ty = threadIdx.y;
    const int d0 = blockIdx.x * 32, s0 = blockIdx.y * 32;
    const size_t rowOff = (size_t)blockIdx.z * SS;
    #pragma unroll
    for (int j = 0; j < 32; j += 8)
        t[ty + j][tx] = Vh[(rowOff + s0 + ty + j) * ND + 2 * DD + d0 + tx];
    __syncthreads();
    const size_t bo = (size_t)blockIdx.z * DD * SS;
    #pragma unroll
    for (int j = 0; j < 32; j += 8)
        Vt[bo + (size_t)(d0 + ty + j) * SS + s0 + tx] = t[tx][ty + j];
}

// 1 / rowsum of unnormalized P (fp16 in, fp32 out); one block per row
__global__ __launch_bounds__(256)
void rowsum_inv_kernel(const fp16* __restrict__ Pu, float* __restrict__ rsinv)
{
    __shared__ float red[256];
    const __half2* row = reinterpret_cast<const __half2*>(Pu + (size_t)blockIdx.x * SS);
    const int tid = threadIdx.x;
    float sum = 0.f;
    #pragma unroll
    for (int i = 0; i < 4; ++i) {
        const float2 p = __half22float2(row[tid + 256 * i]);
        sum += p.x + p.y;
    }
    red[tid] = sum; __syncthreads();
    #pragma unroll
    for (int s = 128; s > 0; s >>= 1) { if (tid < s) red[tid] += red[tid + s]; __syncthreads(); }
    if (tid == 0) rsinv[blockIdx.x] = __frcp_rn(red[0]);
}

// ---------------- launch ----------------
extern "C" void kernel_launch(void* const* d_in, const int* in_sizes, int n_in,
                              void* d_out, int out_size)
{
    const float* x  = (const float*)d_in[0];
    const float* Wq = (const float*)d_in[1];
    const float* bq = (const float*)d_in[2];
    const float* Wk = (const float*)d_in[3];
    const float* bk = (const float*)d_in[4];
    const float* Wv = (const float*)d_in[5];
    const float* bv = (const float*)d_in[6];
    float* out = (float*)d_out;

    fp16 *xh, *Wt, *QKVh, *Vt, *Pu;
    float *bias, *rsinv;
    cudaGetSymbolAddress((void**)&xh, g_xh);
    cudaGetSymbolAddress((void**)&Wt, g_Wt);
    cudaGetSymbolAddress((void**)&QKVh, g_QKVh);
    cudaGetSymbolAddress((void**)&Vt, g_Vt);
    cudaGetSymbolAddress((void**)&Pu, g_Pu);
    cudaGetSymbolAddress((void**)&bias, g_bias);
    cudaGetSymbolAddress((void**)&rsinv, g_rsinv);

    cudaFuncSetAttribute(tc_gemm<1, true>,  cudaFuncAttributeMaxDynamicSharedMemorySize, SMEM_TOTAL);
    cudaFuncSetAttribute(tc_gemm<2, false>, cudaFuncAttributeMaxDynamicSharedMemorySize, SMEM_TOTAL);
    cudaFuncSetAttribute(tc_gemm<3, false>, cudaFuncAttributeMaxDynamicSharedMemorySize, SMEM_TOTAL);

    const long long sQK = (long long)SS * ND;
    const long long sS  = (long long)SS * SS;

    // prep: 3 launches
    round_x_kernel<<<(BB * SS * DD / 4 + 255) / 256, 256>>>((const float4*)x, xh, BB * SS * DD / 4);
    transpose_round_w_all<<<dim3(DD / 32, DD / 32, 3), dim3(32, 8)>>>(Wq, Wk, Wv, Wt);
    concat_bias<<<(ND + 255) / 256, 256>>>(bq, bk, bv, bias);

    // merged QKV projection [16384,3072], fp16 out   (ncu -s 5 lands here)
    dim3 g1(ND / 128, BB * SS / 128, 1);                 // (24, 128)
    tc_gemm<1, true><<<g1, 256, SMEM_TOTAL>>>(xh, Wt, bias, nullptr, nullptr, QKVh,
                                              DD, DD, DD, 0, 0, 0, ND, 1.0f);

    // V -> Vt [b][d][s]
    transpose_v<<<dim3(DD / 32, SS / 32, BB), dim3(32, 8)>>>(QKVh, Vt);

    // Pu = exp((Q K^T)/32), fp16 out — fused softmax numerator
    dim3 g2(SS / 128, SS / 128, BB);                     // (16, 16, 8)
    tc_gemm<2, false><<<g2, 256, SMEM_TOTAL>>>(QKVh, QKVh + DD, nullptr, nullptr,
                                               nullptr, Pu,
                                               DD, ND, ND, sQK, sQK, sS, SS, 0.03125f);

    // rsinv = 1 / rowsum(Pu)
    rowsum_inv_kernel<<<BB * SS, 256>>>(Pu, rsinv);

    // out = (Pu V) * rsinv
    dim3 g3(DD / 128, SS / 128, BB);                     // (8, 16, 8)
    tc_gemm<3, false><<<g3, 256, SMEM_TOTAL>>>(Pu, Vt, nullptr, rsinv,
                                               out, nullptr,
                                               SS, SS, SS, sS, (long long)DD * SS,
                                               (long long)SS * DD, DD, 1.0f);
}

// round 17
// speedup vs baseline: 1.1275x; 1.0740x over previous
#include <cuda_runtime.h>
#include <cuda_fp16.h>
#include <cstdint>
#include <cstddef>

#define BB 8
#define SS 2048
#define DD 1024
#define ND 3072   // merged QKV output width

typedef __half fp16;

// ---------------- scratch ----------------
__device__ fp16 g_xh[(size_t)BB * SS * DD];      // x rounded to fp16
__device__ fp16 g_Wt[(size_t)ND * DD];           // [3072][1024] K-major, rounded fp16
__device__ float g_bias[ND];
__device__ fp16 g_QKVh[(size_t)BB * SS * ND];    // [16384][3072]
__device__ fp16 g_Vt[(size_t)BB * DD * SS];      // [b][d][s]
__device__ fp16 g_Pu[(size_t)BB * SS * SS];      // unnormalized exp(scores), fp16
__device__ float g_rsum[(size_t)BB * SS];        // rowsum(exp(scores)), atomically built

// ---------------- PTX helpers ----------------
__device__ __forceinline__ uint32_t smem_u32(const void* p) {
    uint32_t a;
    asm("{ .reg .u64 t; cvta.to.shared.u64 t, %1; cvt.u32.u64 %0, t; }" : "=r"(a) : "l"(p));
    return a;
}
__device__ __forceinline__ void cp16(uint32_t s, const void* g) {
    asm volatile("cp.async.cg.shared.global [%0], [%1], 16;\n" :: "r"(s), "l"(g));
}
__device__ __forceinline__ void cp_commit() { asm volatile("cp.async.commit_group;\n" ::: "memory"); }
template <int N> __device__ __forceinline__ void cp_wait() {
    asm volatile("cp.async.wait_group %0;\n" :: "n"(N) : "memory");
}
__device__ __forceinline__ void ldsm_x4(uint32_t& r0, uint32_t& r1, uint32_t& r2, uint32_t& r3, uint32_t a) {
    asm volatile("ldmatrix.sync.aligned.m8n8.x4.shared.b16 {%0,%1,%2,%3}, [%4];"
                 : "=r"(r0), "=r"(r1), "=r"(r2), "=r"(r3) : "r"(a));
}
__device__ __forceinline__ void mma16816(float* d,
                                         uint32_t a0, uint32_t a1, uint32_t a2, uint32_t a3,
                                         uint32_t b0, uint32_t b1) {
    asm volatile("mma.sync.aligned.m16n8k16.row.col.f32.f16.f16.f32 "
                 "{%0,%1,%2,%3}, {%4,%5,%6,%7}, {%8,%9}, {%0,%1,%2,%3};"
                 : "+f"(d[0]), "+f"(d[1]), "+f"(d[2]), "+f"(d[3])
                 : "r"(a0), "r"(a1), "r"(a2), "r"(a3), "r"(b0), "r"(b1));
}

#define SW128(o) ((o) ^ (((o) >> 3) & 0x70))

// smem stage: A (16K) + B (16K) = 32K; 3 stages = 96K; 2 CTAs/SM
static constexpr int STAGE = 32768;
static constexpr int STAGES = 3;
static constexpr int SMEM_TOTAL = STAGES * STAGE;   // 98304

// ---------------- 1-pass fp16 mma.sync GEMM, CTA 128x128, 8 warps as 4(m)x2(n),
// warp tile 32x64 (32 HMMA per 6 LDSM per ks). Strength-reduced addressing.
// EPI: 1 = fp16 out (+bias)              [QKV projection]
//      2 = fp16 exp(scale*acc) out + atomic row-sums [scores]
//      3 = fp32 out * rcp(rsum[row])     [PV with deferred softmax normalization]
template <int EPI, bool HASB>
__global__ __launch_bounds__(256, 2)
void tc_gemm(const fp16* __restrict__ A_, const fp16* __restrict__ B_,
             const float* __restrict__ bias, float* __restrict__ rs,
             float* __restrict__ Co, fp16* __restrict__ Coh,
             int Kd, int lda, int ldb,
             long long sA, long long sB, long long sC, int ldo, float scale)
{
    extern __shared__ char smem[];
    const uint32_t su = smem_u32(smem);
    const int tid = threadIdx.x, lane = tid & 31, wid = tid >> 5;
    const int wm = wid >> 1, wn = wid & 1;           // 4(m) x 2(n), warp tile 32x64
    const int rowBase = blockIdx.y * 128, colBase = blockIdx.x * 128;

    A_ += (long long)blockIdx.z * sA;
    B_ += (long long)blockIdx.z * sB;
    if (EPI == 3) { Co += (long long)blockIdx.z * sC; rs += (long long)blockIdx.z * SS; }
    else          Coh += (long long)blockIdx.z * sC;
    if (EPI == 2) rs += (long long)blockIdx.z * SS;

    // ---- per-thread running global pointers (advance 64 elems per chunk) ----
    const int r0 = tid >> 3, cu8 = (tid & 7) * 8;
    const fp16* aptr = A_ + (size_t)(rowBase + r0) * lda + cu8;
    const fp16* bptr = B_ + (size_t)(colBase + r0) * ldb + cu8;
    const size_t aj = (size_t)32 * lda, bj = (size_t)32 * ldb;   // j-stride (32 rows)

    // ---- precomputed swizzled smem store offset (j adds 4096, commutes with SW128) ----
    const uint32_t st0 = SW128((uint32_t)(r0 * 128 + (tid & 7) * 16));
    uint32_t wbase = su;                               // write-stage base, cycles

    auto load_stage = [&]() {
        #pragma unroll
        for (int j = 0; j < 4; ++j)
            cp16(wbase + st0 + j * 4096, aptr + j * aj);
        #pragma unroll
        for (int j = 0; j < 4; ++j)
            cp16(wbase + 16384 + st0 + j * 4096, bptr + j * bj);
        cp_commit();
        aptr += 64; bptr += 64;
        wbase += STAGE; if (wbase == su + SMEM_TOTAL) wbase = su;
    };

    // ---- precomputed swizzled fragment-read offsets per ks ----
    const uint32_t sw   = (lane & 7) << 4;
    const uint32_t arow = (lane & 7) + (lane & 8);
    const uint32_t koff = (lane & 16);
    uint32_t qa[4], qb[4];
    #pragma unroll
    for (int ks = 0; ks < 4; ++ks) {
        qa[ks] = (((uint32_t)(wm * 32 + arow) * 128) + ks * 32 + koff) ^ sw;
        qb[ks] = ((((uint32_t)(wn * 64 + arow) * 128) + ks * 32 + koff) ^ sw) + 16384;
    }

    float acc[16][4] = {};                             // [im*8+in][4], im<2, in<8
    const int NC = Kd >> 6;

    load_stage();
    load_stage();
    uint32_t rbase = su;                               // read-stage base, cycles

    for (int c = 0; c < NC; ++c) {
        cp_wait<1>();
        __syncthreads();                               // single barrier per chunk
        if (c + 2 < NC) load_stage();
        else            cp_commit();                   // keep group counts aligned

        #pragma unroll
        for (int ks = 0; ks < 4; ++ks) {
            uint32_t ah[2][4], bh[4][4];
            #pragma unroll
            for (int im = 0; im < 2; ++im)
                ldsm_x4(ah[im][0], ah[im][1], ah[im][2], ah[im][3],
                        rbase + qa[ks] + im * 2048);
            #pragma unroll
            for (int ip = 0; ip < 4; ++ip)
                ldsm_x4(bh[ip][0], bh[ip][1], bh[ip][2], bh[ip][3],
                        rbase + qb[ks] + ip * 2048);
            #pragma unroll
            for (int im = 0; im < 2; ++im)
                #pragma unroll
                for (int in = 0; in < 8; ++in) {
                    float* d = acc[im * 8 + in];
                    const int ip = in >> 1, sb = in & 1;
                    mma16816(d, ah[im][0], ah[im][1], ah[im][2], ah[im][3],
                             bh[ip][sb], bh[ip][2 + sb]);
                }
        }
        rbase += STAGE; if (rbase == su + SMEM_TOTAL) rbase = su;
    }

    // ---------------- epilogue ----------------
    float rinv[2][2];
    if (EPI == 3) {
        #pragma unroll
        for (int im = 0; im < 2; ++im)
            #pragma unroll
            for (int h = 0; h < 2; ++h)
                rinv[im][h] = __frcp_rn(rs[rowBase + wm * 32 + im * 16 + (lane >> 2) + h * 8]);
    }
    float psum[2][2] = {};                             // EPI==2 partial row sums

    #pragma unroll
    for (int im = 0; im < 2; ++im) {
        #pragma unroll
        for (int in = 0; in < 8; ++in) {
            const float* d = acc[im * 8 + in];
            const int row0 = rowBase + wm * 32 + im * 16 + (lane >> 2);
            const int col0 = colBase + wn * 64 + in * 8 + 2 * (lane & 3);
            #pragma unroll
            for (int h = 0; h < 2; ++h) {
                const int row = row0 + h * 8;
                float v0 = d[2 * h + 0], v1 = d[2 * h + 1];
                if (HASB) { v0 += bias[col0]; v1 += bias[col0 + 1]; }
                v0 *= scale; v1 *= scale;
                if (EPI == 1) {
                    __half2 H; H.x = __float2half(v0); H.y = __float2half(v1);
                    *reinterpret_cast<__half2*>(Coh + (size_t)row * ldo + col0) = H;
                } else if (EPI == 2) {
                    const float e0 = __expf(v0), e1 = __expf(v1);
                    psum[im][h] += e0 + e1;
                    __half2 H; H.x = __float2half(e0); H.y = __float2half(e1);
                    *reinterpret_cast<__half2*>(Coh + (size_t)row * ldo + col0) = H;
                } else {
                    const float r = rinv[im][h];
                    float2 f2; f2.x = v0 * r; f2.y = v1 * r;
                    *reinterpret_cast<float2*>(Co + (size_t)row * ldo + col0) = f2;
                }
            }
        }
    }
    if (EPI == 2) {
        #pragma unroll
        for (int im = 0; im < 2; ++im)
            #pragma unroll
            for (int h = 0; h < 2; ++h)
                atomicAdd(rs + rowBase + wm * 32 + im * 16 + (lane >> 2) + h * 8,
                          psum[im][h]);
    }
}

// ---------------- aux kernels ----------------
__global__ __launch_bounds__(256)
void round_x_kernel(const float4* __restrict__ src, fp16* __restrict__ hi, int n4)
{
    const int i = blockIdx.x * 256 + threadIdx.x;
    if (i >= n4) return;
    const float4 v = src[i];
    __half2 H0; H0.x = __float2half(v.x); H0.y = __float2half(v.y);
    __half2 H1; H1.x = __float2half(v.z); H1.y = __float2half(v.w);
    reinterpret_cast<__half2*>(hi)[2 * i] = H0;
    reinterpret_cast<__half2*>(hi)[2 * i + 1] = H1;
}

// all three W [1024][1024] fp32 -> Wt sections [n][k] fp16 (z selects the matrix)
__global__ __launch_bounds__(256)
void transpose_round_w_all(const float* __restrict__ Wq, const float* __restrict__ Wk,
                           const float* __restrict__ Wv, fp16* __restrict__ T)
{
    __shared__ float t[32][33];
    const float* W = (blockIdx.z == 0) ? Wq : (blockIdx.z == 1) ? Wk : Wv;
    fp16* Td = T + (size_t)blockIdx.z * DD * DD;
    const int tx = threadIdx.x, ty = threadIdx.y;
    const int x0 = blockIdx.x * 32, y0 = blockIdx.y * 32;
    #pragma unroll
    for (int j = 0; j < 32; j += 8)
        t[ty + j][tx] = W[(size_t)(y0 + ty + j) * DD + x0 + tx];
    __syncthreads();
    #pragma unroll
    for (int j = 0; j < 32; j += 8)
        Td[(size_t)(x0 + ty + j) * DD + y0 + tx] = __float2half(t[tx][ty + j]);
}

// bias concat + zero the atomic row-sum accumulator (re-zeroed every replay)
__global__ void concat_bias(const float* bq, const float* bk, const float* bv,
                            float* o, float* rsum)
{
    const int i = blockIdx.x * 256 + threadIdx.x;
    if (i < DD) o[i] = bq[i];
    else if (i < 2 * DD) o[i] = bk[i - DD];
    else if (i < ND) o[i] = bv[i - 2 * DD];
    if (i < BB * SS) rsum[i] = 0.f;
}

// V slice of QKVh (cols 2048..3071) -> Vt[b][d][s]
__global__ __launch_bounds__(256)
void transpose_v(const fp16* __restrict__ Vh, fp16* __restrict__ Vt)
{
    __shared__ fp16 t[32][33];
    const int tx = threadIdx.x, ty = threadIdx.y;
    const int d0 = blockIdx.x * 32, s0 = blockIdx.y * 32;
    const size_t rowOff = (size_t)blockIdx.z * SS;
    #pragma unroll
    for (int j = 0; j < 32; j += 8)
        t[ty + j][tx] = Vh[(rowOff + s0 + ty + j) * ND + 2 * DD + d0 + tx];
    __syncthreads();
    const size_t bo = (size_t)blockIdx.z * DD * SS;
    #pragma unroll
    for (int j = 0; j < 32; j += 8)
        Vt[bo + (size_t)(d0 + ty + j) * SS + s0 + tx] = t[tx][ty + j];
}

// ---------------- launch ----------------
extern "C" void kernel_launch(void* const* d_in, const int* in_sizes, int n_in,
                              void* d_out, int out_size)
{
    const float* x  = (const float*)d_in[0];
    const float* Wq = (const float*)d_in[1];
    const float* bq = (const float*)d_in[2];
    const float* Wk = (const float*)d_in[3];
    const float* bk = (const float*)d_in[4];
    const float* Wv = (const float*)d_in[5];
    const float* bv = (const float*)d_in[6];
    float* out = (float*)d_out;

    fp16 *xh, *Wt, *QKVh, *Vt, *Pu;
    float *bias, *rsum;
    cudaGetSymbolAddress((void**)&xh, g_xh);
    cudaGetSymbolAddress((void**)&Wt, g_Wt);
    cudaGetSymbolAddress((void**)&QKVh, g_QKVh);
    cudaGetSymbolAddress((void**)&Vt, g_Vt);
    cudaGetSymbolAddress((void**)&Pu, g_Pu);
    cudaGetSymbolAddress((void**)&bias, g_bias);
    cudaGetSymbolAddress((void**)&rsum, g_rsum);

    cudaFuncSetAttribute(tc_gemm<1, true>,  cudaFuncAttributeMaxDynamicSharedMemorySize, SMEM_TOTAL);
    cudaFuncSetAttribute(tc_gemm<2, false>, cudaFuncAttributeMaxDynamicSharedMemorySize, SMEM_TOTAL);
    cudaFuncSetAttribute(tc_gemm<3, false>, cudaFuncAttributeMaxDynamicSharedMemorySize, SMEM_TOTAL);

    const long long sQK = (long long)SS * ND;
    const long long sS  = (long long)SS * SS;

    // prep: 3 launches (concat_bias also zeroes rsum for this replay)
    round_x_kernel<<<(BB * SS * DD / 4 + 255) / 256, 256>>>((const float4*)x, xh, BB * SS * DD / 4);
    transpose_round_w_all<<<dim3(DD / 32, DD / 32, 3), dim3(32, 8)>>>(Wq, Wk, Wv, Wt);
    concat_bias<<<(BB * SS + 255) / 256, 256>>>(bq, bk, bv, bias, rsum);

    // merged QKV projection [16384,3072], fp16 out   (ncu -s 5 lands here)
    dim3 g1(ND / 128, BB * SS / 128, 1);                 // (24, 128)
    tc_gemm<1, true><<<g1, 256, SMEM_TOTAL>>>(xh, Wt, bias, nullptr, nullptr, QKVh,
                                              DD, DD, DD, 0, 0, 0, ND, 1.0f);

    // V -> Vt [b][d][s]
    transpose_v<<<dim3(DD / 32, SS / 32, BB), dim3(32, 8)>>>(QKVh, Vt);

    // Pu = exp((Q K^T)/32) + atomic row-sums
    dim3 g2(SS / 128, SS / 128, BB);                     // (16, 16, 8)
    tc_gemm<2, false><<<g2, 256, SMEM_TOTAL>>>(QKVh, QKVh + DD, nullptr, rsum,
                                               nullptr, Pu,
                                               DD, ND, ND, sQK, sQK, sS, SS, 0.03125f);

    // out = (Pu V) * rcp(rsum)
    dim3 g3(DD / 128, SS / 128, BB);                     // (8, 16, 8)
    tc_gemm<3, false><<<g3, 256, SMEM_TOTAL>>>(Pu, Vt, nullptr, rsum,
                                               out, nullptr,
                                               SS, SS, SS, sS, (long long)DD * SS,
                                               (long long)SS * DD, DD, 1.0f);
}